// round 13
// baseline (speedup 1.0000x reference)
#include <cuda_runtime.h>
#include <string.h>

// Per-channel 5x5 correlation, stride=1, pad=2; 128 planes of 512x512 f32.
// R11 structure (champion) with ONE change: cp.async.cg row staging.
//   - 4 warps/CTA (block 128), 2048 CTAs; warp owns a 256x16 strip.
//   - per-warp 5-slot smem row ring, depth-4 cp.async prefetch.
//   - partial prologue/epilogue accsteps (1600 FMA2/strip).
//   - cp.async.cg: staged rows are only read back through smem, so L1
//     allocation of them (with .ca) was pure l1tex overhead (L1=79.7% in R11).

#define IMG   512
#define R     16
#define NSTEP (R + 4)          // 20 input rows per strip
#define ROWB  1056             // 264 floats per staged row
#define RING  5
#define WSM   (RING * ROWB)    // 5280 B per warp

typedef unsigned long long u64;

__device__ __forceinline__ u64 pk(float lo, float hi) {
    float2 t; t.x = lo; t.y = hi;
    u64 r; memcpy(&r, &t, 8);
    return r;
}
__device__ __forceinline__ u64 pk2(float2 t) {
    u64 r; memcpy(&r, &t, 8);
    return r;
}
__device__ __forceinline__ u64 fma2(u64 a, u64 b, u64 c) {
    u64 d;
    asm("fma.rn.f32x2 %0, %1, %2, %3;" : "=l"(d) : "l"(a), "l"(b), "l"(c));
    return d;
}
__device__ __forceinline__ u64 mul2(u64 a, u64 b) {
    u64 d;
    asm("mul.rn.f32x2 %0, %1, %2;" : "=l"(d) : "l"(a), "l"(b));
    return d;
}
__device__ __forceinline__ void cpa16(unsigned d, const void* g) {
    asm volatile("cp.async.cg.shared.global [%0], [%1], 16;" :: "r"(d), "l"(g));
}
__device__ __forceinline__ void stsz(unsigned a) {
    asm volatile("st.shared.v4.u32 [%0], {%1,%1,%1,%1};" :: "r"(a), "r"(0u));
}

// Taps of input-row s (I = s mod 5) into pending output slots, restricted to
// kernel rows kr in [KRLO, KRHI]. Output o = s - kr lives in slot o % 5.
// kr==0 is an output's chronologically FIRST contribution: overwrite via mul.
template<int I, int KRLO, int KRHI>
__device__ __forceinline__ void accstep(u64 acc[5][4],
                                        const u64* __restrict__ wp,
                                        const u64* __restrict__ p) {
    #pragma unroll
    for (int kr = KRLO; kr <= KRHI; kr++) {
        const int slot = ((I - kr) % 5 + 5) % 5;
        #pragma unroll
        for (int t = 0; t < 5; t++) {
            #pragma unroll
            for (int pj = 0; pj < 4; pj++) {
                if (kr == 0 && t == 0)
                    acc[slot][pj] = mul2(wp[0], p[2 * pj]);
                else
                    acc[slot][pj] = fma2(wp[kr * 5 + t], p[2 * pj + t], acc[slot][pj]);
            }
        }
    }
}

__global__ __launch_bounds__(128, 6) void conv5x5_kernel(
    const float* __restrict__ X,
    const float* __restrict__ Kw,
    float* __restrict__ Out)
{
    __shared__ __align__(16) char ring[4 * WSM];

    const int lane  = threadIdx.x;
    const int wrp   = threadIdx.y;                  // 0..3
    const int c     = blockIdx.z;
    const int warpX = blockIdx.x;                   // 0..1
    const int strip = blockIdx.y * 4 + wrp;         // 0..31
    const int Y0    = strip * R;
    const int x0w   = warpX * 256;                  // warp x base
    const int x0    = x0w + lane * 8;               // lane x base

    const float* __restrict__ Xc = X   + (size_t)c * (IMG * IMG);
    float*       __restrict__ Oc = Out + (size_t)c * (IMG * IMG);

    const char* wring = ring + wrp * WSM;                       // generic, for LDS
    const unsigned sbase =
        (unsigned)__cvta_generic_to_shared(ring) + wrp * WSM;   // for cp.async/STS

    // zero the permanently-out-of-image x-edge chunk of every ring slot ONCE:
    // chunk 0 (x0w-4..-1) for warpX==0, chunk 65 (x 512..515) for warpX==1.
    if (lane < RING)
        stsz(sbase + lane * ROWB + (warpX ? 65 * 16 : 0));
    __syncwarp();

    // packed (w,w) weights (warp-uniform -> UR promotion)
    u64 wp[25];
    #pragma unroll
    for (int i = 0; i < 25; i++) { const float wv = __ldg(&Kw[i]); wp[i] = pk(wv, wv); }

    u64 acc[5][4];
    #pragma unroll
    for (int j = 0; j < 5; j++)
        #pragma unroll
        for (int q = 0; q < 4; q++) acc[j][q] = 0ull;   // slots start via mul anyway

    u64 p[11];

// Issue async fill of row ROWI into ring slot SLOT; always ends with a
// commit_group (possibly empty) so group counting stays uniform.
// Row covers global x = x0w-4 .. x0w+259 (66 x 16B chunks); the one
// permanently-OOB edge chunk is skipped (pre-zeroed above).
#define ISSUE_ROW(ROWI, SLOT) do {                                             \
    const int row_ = (ROWI);                                                   \
    if (row_ < NSTEP) {                                                        \
        const int gy_ = Y0 - 2 + row_;                                         \
        const unsigned sb_ = sbase + (SLOT) * ROWB;                            \
        if ((unsigned)gy_ < (unsigned)IMG) {                                   \
            const char* gs_ = (const char*)(Xc + (size_t)gy_ * IMG + x0w - 4); \
            if ((lane | warpX) != 0)                                           \
                cpa16(sb_ + lane * 16, gs_ + lane * 16);                       \
            cpa16(sb_ + (32 + lane) * 16, gs_ + (32 + lane) * 16);             \
            if (lane + warpX < 2)                                              \
                cpa16(sb_ + (64 + lane) * 16, gs_ + (64 + lane) * 16);         \
        } else {                                                               \
            stsz(sb_ + lane * 16);                                             \
            stsz(sb_ + (32 + lane) * 16);                                      \
            if (lane < 2) stsz(sb_ + (64 + lane) * 16);                        \
        }                                                                      \
    }                                                                          \
    asm volatile("cp.async.commit_group;");                                    \
} while (0)

// Read ring slot SLOT and pack p[0..10]. Lane window v[-2..9] = bytes
// lane*32+8 .. +55. Even pairs = aligned load results (no MOVs).
#define READPACK(SLOT) do {                                                    \
    const char* b_ = wring + (SLOT) * ROWB + lane * 32;                        \
    const float2 h0 = *reinterpret_cast<const float2*>(b_ + 8);                \
    const float4 A  = *reinterpret_cast<const float4*>(b_ + 16);               \
    const float4 B  = *reinterpret_cast<const float4*>(b_ + 32);               \
    const float2 h1 = *reinterpret_cast<const float2*>(b_ + 48);               \
    p[0]  = pk2(h0);                                                           \
    p[1]  = pk(h0.y, A.x);                                                     \
    p[2]  = pk(A.x,  A.y);                                                     \
    p[3]  = pk(A.y,  A.z);                                                     \
    p[4]  = pk(A.z,  A.w);                                                     \
    p[5]  = pk(A.w,  B.x);                                                     \
    p[6]  = pk(B.x,  B.y);                                                     \
    p[7]  = pk(B.y,  B.z);                                                     \
    p[8]  = pk(B.z,  B.w);                                                     \
    p[9]  = pk(B.w,  h1.x);                                                    \
    p[10] = pk2(h1);                                                           \
} while (0)

#define STORE_ROW(S) do {                                                      \
    float* op_ = Oc + (size_t)(Y0 + (S) - 4) * IMG + x0;                       \
    *reinterpret_cast<ulonglong2*>(op_) =                                      \
        *reinterpret_cast<ulonglong2*>(&acc[((S)+1)%5][0]);                    \
    *reinterpret_cast<ulonglong2*>(op_ + 4) =                                  \
        *reinterpret_cast<ulonglong2*>(&acc[((S)+1)%5][2]);                    \
} while (0)

// Generic step with literal S and kr-range: issue row S+4 (depth-4), wait,
// read+pack row S, accumulate only useful kernel rows, store output S-4.
#define PSTEP(S, KRLO, KRHI) do {                                              \
    ISSUE_ROW((S) + 4, ((S) + 4) % 5);                                         \
    asm volatile("cp.async.wait_group 4;");                                    \
    __syncwarp();                                                              \
    READPACK((S) % 5);                                                         \
    accstep<(S) % 5, KRLO, KRHI>(acc, wp, p);                                  \
    if ((S) >= 4) STORE_ROW(S);                                                \
} while (0)

// Loop step: s = sb + J, sb % 5 == 4 -> all mod-5 indices are literals of J.
#define LSTEP(J) do {                                                          \
    const int s_ = sb + (J);                                                   \
    ISSUE_ROW(s_ + 4, ((J) + 3) % 5);                                          \
    asm volatile("cp.async.wait_group 4;");                                    \
    __syncwarp();                                                              \
    READPACK(((J) + 4) % 5);                                                   \
    accstep<((J) + 4) % 5, 0, 4>(acc, wp, p);                                  \
    {                                                                          \
        float* op_ = Oc + (size_t)(Y0 + s_ - 4) * IMG + x0;                    \
        *reinterpret_cast<ulonglong2*>(op_) =                                  \
            *reinterpret_cast<ulonglong2*>(&acc[(J) % 5][0]);                  \
        *reinterpret_cast<ulonglong2*>(op_ + 4) =                              \
            *reinterpret_cast<ulonglong2*>(&acc[(J) % 5][2]);                  \
    }                                                                          \
} while (0)

    // prologue: issue rows 0..3 (4 groups in flight)
    ISSUE_ROW(0, 0);
    ISSUE_ROW(1, 1);
    ISSUE_ROW(2, 2);
    ISSUE_ROW(3, 3);

    // warm-up steps 0..3: only kr <= s feeds real outputs
    PSTEP(0, 0, 0);
    PSTEP(1, 0, 1);
    PSTEP(2, 0, 2);
    PSTEP(3, 0, 3);

    // full steps 4..13 (two 5-blocks; sb = 4, 9)
    #pragma unroll 1
    for (int sb = 4; sb < 14; sb += 5) {
        LSTEP(0); LSTEP(1); LSTEP(2); LSTEP(3); LSTEP(4);
    }

    // full steps 14, 15
    PSTEP(14, 0, 4);
    PSTEP(15, 0, 4);

    // drain steps 16..19: only kr >= s-15 feeds real outputs
    PSTEP(16, 1, 4);
    PSTEP(17, 2, 4);
    PSTEP(18, 3, 4);
    PSTEP(19, 4, 4);

#undef LSTEP
#undef PSTEP
#undef STORE_ROW
#undef READPACK
#undef ISSUE_ROW
}

extern "C" void kernel_launch(void* const* d_in, const int* in_sizes, int n_in,
                              void* d_out, int out_size)
{
    const float* X  = (const float*)d_in[0];
    const float* Kw = (const float*)d_in[1];
    float* Out      = (float*)d_out;

    dim3 grid(2, IMG / R / 4, 128);   // 2 x-halves, 8 strip-groups, 128 planes = 2048 CTAs
    dim3 block(32, 4);                // 4 warps, each owns one 256x16 strip
    conv5x5_kernel<<<grid, block>>>(X, Kw, Out);
}

// round 14
// speedup vs baseline: 1.1231x; 1.1231x over previous
#include <cuda_runtime.h>
#include <string.h>

// Per-channel 5x5 correlation, stride=1, pad=2; 128 planes of 512x512 f32.
// Register-buffered rolling kernel (R9 structure) + partial accstep trim:
//   - 4 warps/CTA, warp owns a 256-wide x 16-row strip; lane owns 8 x.
//   - per input row: 2 aligned LDG.128 + 4 warp shuffles for +-2 x halo
//     (warp-edge lanes do tiny predicated float2 gmem loads). No shared mem
//     staging: ~16 L1 wavefronts/step vs ~28 for the cp.async ring.
//   - depth-2 row prefetch (double-buffered raw regs, parity compile-time).
//   - PARTIAL warm/drain accsteps: step s runs only kernel rows
//     kr in [max(0,s-15), min(4,s)] -> 1600 instead of 2000 FMA2 per strip,
//     bit-identical for stored outputs (kr==0 mul2 is still each output's
//     chronologically first contribution).
//   - 5 pending output rows in registers, mod-5 rotation; completed row
//     stored straight from acc (ulonglong2 bit-cast).

#define IMG  512
#define R    16
#define NSTEP (R + 4)      // 20 input rows per strip
#define FULLMASK 0xffffffffu

typedef unsigned long long u64;

__device__ __forceinline__ u64 pk(float lo, float hi) {
    float2 t; t.x = lo; t.y = hi;
    u64 r; memcpy(&r, &t, 8);
    return r;
}
__device__ __forceinline__ u64 fma2(u64 a, u64 b, u64 c) {
    u64 d;
    asm("fma.rn.f32x2 %0, %1, %2, %3;" : "=l"(d) : "l"(a), "l"(b), "l"(c));
    return d;
}
__device__ __forceinline__ u64 mul2(u64 a, u64 b) {
    u64 d;
    asm("mul.rn.f32x2 %0, %1, %2;" : "=l"(d) : "l"(a), "l"(b));
    return d;
}

// Taps of input-row s (I = s mod 5) into pending output slots, restricted to
// kernel rows kr in [KRLO, KRHI]. Output o = s - kr lives in slot o % 5.
// kr==0 is an output's chronologically FIRST contribution: overwrite via mul.
template<int I, int KRLO, int KRHI>
__device__ __forceinline__ void accstep(u64 acc[5][4],
                                        const u64* __restrict__ wp,
                                        const u64* __restrict__ p) {
    #pragma unroll
    for (int kr = KRLO; kr <= KRHI; kr++) {
        const int slot = ((I - kr) % 5 + 5) % 5;
        #pragma unroll
        for (int t = 0; t < 5; t++) {
            #pragma unroll
            for (int pj = 0; pj < 4; pj++) {
                if (kr == 0 && t == 0)
                    acc[slot][pj] = mul2(wp[0], p[2 * pj]);
                else
                    acc[slot][pj] = fma2(wp[kr * 5 + t], p[2 * pj + t], acc[slot][pj]);
            }
        }
    }
}

__global__ __launch_bounds__(128, 5) void conv5x5_kernel(
    const float* __restrict__ X,
    const float* __restrict__ Kw,
    float* __restrict__ Out)
{
    const int lane  = threadIdx.x;
    const int wrp   = threadIdx.y;                  // 0..3
    const int c     = blockIdx.z;
    const int warpX = blockIdx.x;                   // 0..1
    const int strip = blockIdx.y * 4 + wrp;         // 0..31
    const int Y0    = strip * R;
    const int x0    = warpX * 256 + lane * 8;

    const float* __restrict__ Xc = X   + (size_t)c * (IMG * IMG);
    float*       __restrict__ Oc = Out + (size_t)c * (IMG * IMG);

    // packed (w,w) weights (warp-uniform -> UR promotion)
    u64 wp[25];
    #pragma unroll
    for (int i = 0; i < 25; i++) { const float wv = __ldg(&Kw[i]); wp[i] = pk(wv, wv); }

    u64 acc[5][4];
    #pragma unroll
    for (int j = 0; j < 5; j++)
        #pragma unroll
        for (int q = 0; q < 4; q++) acc[j][q] = 0ull;   // slots start via mul anyway

    u64 p[11];
    float4 Ab[2], Bb[2];      // double-buffered raw rows
    float2 LFb[2], RFb[2];

// Load input row S into buffer PAR (zero outside image / past strip).
#define LOADROW(S, PAR) do {                                                   \
    const int s__ = (S);                                                       \
    const int gy_ = Y0 - 2 + s__;                                              \
    Ab[PAR] = make_float4(0.f,0.f,0.f,0.f); Bb[PAR] = make_float4(0.f,0.f,0.f,0.f); \
    LFb[PAR] = make_float2(0.f,0.f); RFb[PAR] = make_float2(0.f,0.f);          \
    if (s__ < NSTEP && (unsigned)gy_ < (unsigned)IMG) {                        \
        const float* rp_ = Xc + (size_t)gy_ * IMG + x0;                        \
        Ab[PAR] = *reinterpret_cast<const float4*>(rp_);                       \
        Bb[PAR] = *reinterpret_cast<const float4*>(rp_ + 4);                   \
        if (lane == 0  && x0 >= 2)      LFb[PAR] = *reinterpret_cast<const float2*>(rp_ - 2); \
        if (lane == 31 && x0 + 9 < IMG) RFb[PAR] = *reinterpret_cast<const float2*>(rp_ + 8); \
    }                                                                          \
} while (0)

// Shuffle halo + pack buffer PAR into p[0..10].
#define PACKROW(PAR) do {                                                      \
    float l0_ = __shfl_up_sync(FULLMASK,  Bb[PAR].z, 1);                       \
    float l1_ = __shfl_up_sync(FULLMASK,  Bb[PAR].w, 1);                       \
    float r0_ = __shfl_down_sync(FULLMASK, Ab[PAR].x, 1);                      \
    float r1_ = __shfl_down_sync(FULLMASK, Ab[PAR].y, 1);                      \
    if (lane == 0)  { l0_ = LFb[PAR].x; l1_ = LFb[PAR].y; }                    \
    if (lane == 31) { r0_ = RFb[PAR].x; r1_ = RFb[PAR].y; }                    \
    p[0]  = pk(l0_, l1_);             p[1]  = pk(l1_, Ab[PAR].x);              \
    p[2]  = pk(Ab[PAR].x, Ab[PAR].y); p[3]  = pk(Ab[PAR].y, Ab[PAR].z);        \
    p[4]  = pk(Ab[PAR].z, Ab[PAR].w); p[5]  = pk(Ab[PAR].w, Bb[PAR].x);        \
    p[6]  = pk(Bb[PAR].x, Bb[PAR].y); p[7]  = pk(Bb[PAR].y, Bb[PAR].z);        \
    p[8]  = pk(Bb[PAR].z, Bb[PAR].w); p[9]  = pk(Bb[PAR].w, r0_);              \
    p[10] = pk(r0_, r1_);                                                      \
} while (0)

#define STORE_ROW(S, SLOT) do {                                                \
    float* op_ = Oc + (size_t)(Y0 + (S) - 4) * IMG + x0;                       \
    *reinterpret_cast<ulonglong2*>(op_) =                                      \
        *reinterpret_cast<ulonglong2*>(&acc[SLOT][0]);                         \
    *reinterpret_cast<ulonglong2*>(op_ + 4) =                                  \
        *reinterpret_cast<ulonglong2*>(&acc[SLOT][2]);                         \
} while (0)

// Generic step, literal S and kr-range: prefetch row S+2 into buf[S&1];
// accumulate row S (in p); store output S-4 from slot (S+1)%5; pack row S+1.
#define GSTEP(S, KRLO, KRHI) do {                                              \
    LOADROW((S) + 2, (S) & 1);                                                 \
    accstep<(S) % 5, KRLO, KRHI>(acc, wp, p);                                  \
    if ((S) >= 4) STORE_ROW((S), ((S)+1) % 5);                                 \
    if ((S) + 1 < NSTEP) PACKROW(((S) + 1) & 1);                               \
} while (0)

// Loop step: S = sb + J, sb even multiple-of-10 base -> all indices literal.
#define LSTEP(J) do {                                                          \
    const int s_ = sb + (J);                                                   \
    LOADROW(s_ + 2, (J) & 1);                                                  \
    accstep<((J) + 4) % 5, 0, 4>(acc, wp, p);                                  \
    {                                                                          \
        float* op_ = Oc + (size_t)(Y0 + s_ - 4) * IMG + x0;                    \
        *reinterpret_cast<ulonglong2*>(op_) =                                  \
            *reinterpret_cast<ulonglong2*>(&acc[(J) % 5][0]);                  \
        *reinterpret_cast<ulonglong2*>(op_ + 4) =                              \
            *reinterpret_cast<ulonglong2*>(&acc[(J) % 5][2]);                  \
    }                                                                          \
    PACKROW(((J) + 1) & 1);                                                    \
} while (0)

    // prologue: rows 0,1 into buffers; pack row 0
    LOADROW(0, 0);
    LOADROW(1, 1);
    PACKROW(0);

    // warm-up steps 0..3: only kr <= s feeds real outputs
    GSTEP(0, 0, 0);
    GSTEP(1, 0, 1);
    GSTEP(2, 0, 2);
    GSTEP(3, 0, 3);

    // full steps 4..13 (single unrolled 10-block; sb = 4 even -> parity literal)
    #pragma unroll 1
    for (int sb = 4; sb < 14; sb += 10) {
        LSTEP(0); LSTEP(1); LSTEP(2); LSTEP(3); LSTEP(4);
        LSTEP(5); LSTEP(6); LSTEP(7); LSTEP(8); LSTEP(9);
    }

    // full steps 14, 15
    GSTEP(14, 0, 4);
    GSTEP(15, 0, 4);

    // drain steps 16..19: only kr >= s-15 feeds real outputs
    GSTEP(16, 1, 4);
    GSTEP(17, 2, 4);
    GSTEP(18, 3, 4);
    GSTEP(19, 4, 4);

#undef LSTEP
#undef GSTEP
#undef STORE_ROW
#undef PACKROW
#undef LOADROW
}

extern "C" void kernel_launch(void* const* d_in, const int* in_sizes, int n_in,
                              void* d_out, int out_size)
{
    const float* X  = (const float*)d_in[0];
    const float* Kw = (const float*)d_in[1];
    float* Out      = (float*)d_out;

    dim3 grid(2, IMG / R / 4, 128);   // 2 x-halves, 8 strip-groups, 128 planes = 2048 CTAs
    dim3 block(32, 4);                // 4 warps, each owns one 256x16 strip
    conv5x5_kernel<<<grid, block>>>(X, Kw, Out);
}